// round 14
// baseline (speedup 1.0000x reference)
#include <cuda_runtime.h>

#define D 128
#define PMAX 512
#define START_SZ 16384
#define RPW 4

__device__ float g_vtab[PMAX * D];
__device__ float g_ctab[PMAX];
__device__ int   g_start[START_SZ];
__device__ int   g_lastb;

// ---------------------------------------------------------------------------
// Kernel 0: segment boundaries + last segment id (batch is int32)
// ---------------------------------------------------------------------------
__global__ void k_bounds(const int* __restrict__ batch, int n) {
    int i = blockIdx.x * blockDim.x + threadIdx.x;
    if (i >= n) return;
    int b = batch[i];
    if (i == 0 || batch[i - 1] != b) {
        if (b >= 0 && b < START_SZ) g_start[b] = i;
    }
    if (i == n - 1) g_lastb = b;
}

// ---------------------------------------------------------------------------
// Kernel 1: per-position fused weight table
// ---------------------------------------------------------------------------
__global__ void k_table(const float* __restrict__ W1, const float* __restrict__ b1,
                        const float* __restrict__ W2, const float* __restrict__ b2) {
    __shared__ float eff[D];
    int p = blockIdx.x;
    int t = threadIdx.x;
    if (t < D / 2) {
        double theta = pow(10000.0, -2.0 * t / (double)D);
        double ang = (double)p * theta;
        double c = cos(ang), s = sin(ang);
        float w0 = W2[2 * t], w1 = W2[2 * t + 1];
        eff[2 * t]     = (float)(w0 * c + w1 * s);
        eff[2 * t + 1] = (float)(w1 * c - w0 * s);
    }
    __syncthreads();
    float acc = 0.f;
#pragma unroll 8
    for (int d = 0; d < D; d++)
        acc = fmaf(W1[d * D + t], eff[d], acc);
    g_vtab[p * D + t] = acc;
    if (t == 0) {
        float cb = b2[0];
        for (int d = 0; d < D; d++) cb = fmaf(b1[d], eff[d], cb);
        g_ctab[p] = cb;
    }
}

// ---------------------------------------------------------------------------
// Slow path (pos >= PMAX, never expected on this input)
// ---------------------------------------------------------------------------
__device__ float row_slow(const float4 xv, int pos,
                          const float* __restrict__ W1,
                          const float* __restrict__ b1,
                          const float* __restrict__ W2,
                          const float* __restrict__ b2, int lane) {
    float4 w2v = reinterpret_cast<const float4*>(W2)[lane];
    float eff0, eff1, eff2, eff3;
    {
        int j0 = 2 * lane;
        double th0 = pow(10000.0, -2.0 * j0 / (double)D);
        double a0 = (double)pos * th0;
        double c0 = cos(a0), s0 = sin(a0);
        eff0 = (float)(w2v.x * c0 + w2v.y * s0);
        eff1 = (float)(w2v.y * c0 - w2v.x * s0);
        int j1 = 2 * lane + 1;
        double th1 = pow(10000.0, -2.0 * j1 / (double)D);
        double a1 = (double)pos * th1;
        double c1 = cos(a1), s1 = sin(a1);
        eff2 = (float)(w2v.z * c1 + w2v.w * s1);
        eff3 = (float)(w2v.w * c1 - w2v.z * s1);
    }
    float4 acc = make_float4(0.f, 0.f, 0.f, 0.f);
    const float4* W1r = reinterpret_cast<const float4*>(W1);
    for (int src = 0; src < 32; src++) {
        float e0 = __shfl_sync(0xffffffffu, eff0, src);
        float e1 = __shfl_sync(0xffffffffu, eff1, src);
        float e2 = __shfl_sync(0xffffffffu, eff2, src);
        float e3 = __shfl_sync(0xffffffffu, eff3, src);
        float4 a = W1r[(4 * src + 0) * (D / 4) + lane];
        acc.x = fmaf(a.x, e0, acc.x); acc.y = fmaf(a.y, e0, acc.y);
        acc.z = fmaf(a.z, e0, acc.z); acc.w = fmaf(a.w, e0, acc.w);
        float4 bq = W1r[(4 * src + 1) * (D / 4) + lane];
        acc.x = fmaf(bq.x, e1, acc.x); acc.y = fmaf(bq.y, e1, acc.y);
        acc.z = fmaf(bq.z, e1, acc.z); acc.w = fmaf(bq.w, e1, acc.w);
        float4 cq = W1r[(4 * src + 2) * (D / 4) + lane];
        acc.x = fmaf(cq.x, e2, acc.x); acc.y = fmaf(cq.y, e2, acc.y);
        acc.z = fmaf(cq.z, e2, acc.z); acc.w = fmaf(cq.w, e2, acc.w);
        float4 dq = W1r[(4 * src + 3) * (D / 4) + lane];
        acc.x = fmaf(dq.x, e3, acc.x); acc.y = fmaf(dq.y, e3, acc.y);
        acc.z = fmaf(dq.z, e3, acc.z); acc.w = fmaf(dq.w, e3, acc.w);
    }
    float4 b1v = reinterpret_cast<const float4*>(b1)[lane];
    float partial = xv.x * acc.x + xv.y * acc.y + xv.z * acc.z + xv.w * acc.w
                  + b1v.x * eff0 + b1v.y * eff1 + b1v.z * eff2 + b1v.w * eff3;
#pragma unroll
    for (int o = 16; o; o >>= 1) partial += __shfl_xor_sync(0xffffffffu, partial, o);
    return partial + b2[0];
}

// ---------------------------------------------------------------------------
// Group state (kept fully in registers; two instances = 2-deep pipeline)
// ---------------------------------------------------------------------------
struct Grp {
    float4 xv[RPW];
    float4 vv[RPW];
    int    pos[RPW];
    int    i0, nr;
};

__device__ __forceinline__ void grp_load(Grp& G, int g, int n, int lane, int lastb,
                                         const float4* __restrict__ x4,
                                         const int*    __restrict__ batch) {
    G.i0 = g * RPW;
    G.nr = min(RPW, n - G.i0);

    int pos_l = 0;
    if (lane < G.nr) {
        int i = G.i0 + lane;
        int b = __ldg(&batch[i]);
        if (b != lastb) {
            int st;
            if (b >= 0 && b < START_SZ) {
                st = g_start[b];
            } else {
                int lo = 0, hi = i;
                while (lo < hi) {
                    int mid = (lo + hi) >> 1;
                    if (batch[mid] < b) lo = mid + 1; else hi = mid;
                }
                st = lo;
            }
            pos_l = i - st;
        }
    }
    const float4* v4 = reinterpret_cast<const float4*>(g_vtab);
#pragma unroll
    for (int r = 0; r < RPW; r++) {
        G.pos[r] = __shfl_sync(0xffffffffu, pos_l, r);
        if (r < G.nr) {
            int p = G.pos[r] < PMAX ? G.pos[r] : 0;
            G.xv[r] = __ldcs(&x4[(size_t)(G.i0 + r) * (D / 4) + lane]);
            G.vv[r] = v4[p * (D / 4) + lane];
        }
    }
}

__device__ __forceinline__ void grp_compute(Grp& G, int lane,
                                            const float* __restrict__ W1,
                                            const float* __restrict__ b1,
                                            const float* __restrict__ W2,
                                            const float* __restrict__ b2,
                                            float* __restrict__ out) {
    float partial[RPW];
    bool any_slow = false;
#pragma unroll
    for (int r = 0; r < RPW; r++) {
        partial[r] = (r < G.nr)
            ? G.xv[r].x * G.vv[r].x + G.xv[r].y * G.vv[r].y
            + G.xv[r].z * G.vv[r].z + G.xv[r].w * G.vv[r].w
            : 0.f;
        if (G.pos[r] >= PMAX && r < G.nr) any_slow = true;
    }
#pragma unroll
    for (int o = 16; o; o >>= 1) {
#pragma unroll
        for (int r = 0; r < RPW; r++)
            partial[r] += __shfl_xor_sync(0xffffffffu, partial[r], o);
    }
    float res_l = 0.f;
#pragma unroll
    for (int r = 0; r < RPW; r++) {
        float v;
        if (any_slow && G.pos[r] >= PMAX && r < G.nr) {
            v = row_slow(G.xv[r], G.pos[r], W1, b1, W2, b2, lane);
        } else {
            v = partial[r] + ((r < G.nr) ? g_ctab[G.pos[r] < PMAX ? G.pos[r] : 0] : 0.f);
        }
        if (lane == r) res_l = v;
    }
    if (lane < G.nr) out[G.i0 + lane] = res_l;
}

// ---------------------------------------------------------------------------
// Kernel 2: persistent warps, grid-stride over groups, 2-deep pipeline
// ---------------------------------------------------------------------------
__global__ __launch_bounds__(256)
void k_main(const float* __restrict__ x,
            const int* __restrict__ batch,
            const float* __restrict__ W1,
            const float* __restrict__ b1,
            const float* __restrict__ W2,
            const float* __restrict__ b2,
            float* __restrict__ out, int n) {
    int lane = threadIdx.x & 31;
    int warp = (int)((blockIdx.x * blockDim.x + threadIdx.x) >> 5);
    int nwarps = (int)((gridDim.x * blockDim.x) >> 5);
    int ngroups = (n + RPW - 1) / RPW;
    const float4* x4 = reinterpret_cast<const float4*>(x);
    int lastb = g_lastb;

    int g0 = warp;
    if (g0 >= ngroups) return;

    Grp A, B;
    grp_load(A, g0, n, lane, lastb, x4, batch);
    for (;;) {
        int g1 = g0 + nwarps;
        if (g1 < ngroups) grp_load(B, g1, n, lane, lastb, x4, batch);
        grp_compute(A, lane, W1, b1, W2, b2, out);
        if (g1 >= ngroups) return;

        int g2 = g1 + nwarps;
        if (g2 < ngroups) grp_load(A, g2, n, lane, lastb, x4, batch);
        grp_compute(B, lane, W1, b1, W2, b2, out);
        if (g2 >= ngroups) return;
        g0 = g2;
    }
}

// ---------------------------------------------------------------------------
extern "C" void kernel_launch(void* const* d_in, const int* in_sizes, int n_in,
                              void* d_out, int out_size) {
    const float* x     = (const float*)d_in[0];
    const int*   batch = (const int*)d_in[1];   // int32 (JAX x64 disabled)
    const float* W1    = (const float*)d_in[2];
    const float* b1    = (const float*)d_in[3];
    const float* W2    = (const float*)d_in[4];
    const float* b2    = (const float*)d_in[5];
    float*       out   = (float*)d_out;
    int n = in_sizes[1];

    k_bounds<<<(n + 255) / 256, 256>>>(batch, n);
    k_table<<<PMAX, D>>>(W1, b1, W2, b2);
    k_main<<<2048, 256>>>(x, batch, W1, b1, W2, b2, out, n);
}

// round 15
// speedup vs baseline: 1.6761x; 1.6761x over previous
#include <cuda_runtime.h>
#include <cstdint>

#define D 128
#define PMAX 512
#define START_SZ 16384
#define TILE 64                    // rows per tile
#define TILE_BYTES (TILE * D * 4)  // 32768
#define STAGES 3
#define NCTA 296
#define NTHREADS 288               // 9 warps: 0-7 consume, 8 produces

// smem layout (bytes)
#define SM_XBUF   0
#define SM_SBUF   (STAGES * TILE_BYTES)                 // 98304
#define SM_FULL   (SM_SBUF + STAGES * TILE * 4)         // 99072
#define SM_EMPTY  (SM_FULL + STAGES * 8)                // 99096
#define SM_TOTAL  (SM_EMPTY + STAGES * 8 + 8)           // 99128 -> pad
#define SMEM_BYTES 99328

__device__ float g_vtab[PMAX * D];
__device__ float g_ctab[PMAX];
__device__ int   g_start[START_SZ];
__device__ int   g_lastb;

// ---------------------------------------------------------------------------
// mbarrier helpers
// ---------------------------------------------------------------------------
__device__ __forceinline__ uint32_t smem_u32(const void* p) {
    uint32_t a;
    asm("{ .reg .u64 t; cvta.to.shared.u64 t, %1; cvt.u32.u64 %0, t; }" : "=r"(a) : "l"(p));
    return a;
}
#define MBAR_INIT(a, c)  asm volatile("mbarrier.init.shared.b64 [%0], %1;" :: "r"(a), "r"(c) : "memory")
#define MBAR_ARRIVE(a)   asm volatile("mbarrier.arrive.shared.b64 _, [%0];" :: "r"(a) : "memory")
#define MBAR_EXPECT_TX(a, b) \
    asm volatile("mbarrier.arrive.expect_tx.shared.b64 _, [%0], %1;" :: "r"(a), "r"(b) : "memory")
#define MBAR_WAIT(a, ph) do {                                                        \
    asm volatile(                                                                    \
        "{\n\t.reg .pred P;\n\t"                                                     \
        "W%=:\n\t"                                                                   \
        "mbarrier.try_wait.parity.acquire.cta.shared::cta.b64 P, [%0], %1, 0x989680;\n\t" \
        "@P bra D%=;\n\t"                                                            \
        "bra W%=;\n\t"                                                               \
        "D%=:\n\t}"                                                                  \
        :: "r"(a), "r"(ph) : "memory");                                              \
} while (0)
#define BULK_G2S(dst, src, bytes, mbar)                                              \
    asm volatile(                                                                    \
        "cp.async.bulk.shared::cluster.global.mbarrier::complete_tx::bytes "         \
        "[%0], [%1], %2, [%3];"                                                      \
        :: "r"(dst), "l"(src), "r"(bytes), "r"(mbar) : "memory")

// ---------------------------------------------------------------------------
// Kernel 0: fused prep — blocks [0,PMAX) build the table, rest scan bounds
// ---------------------------------------------------------------------------
__global__ void k_prep(const int* __restrict__ batch, int n,
                       const float* __restrict__ W1, const float* __restrict__ b1,
                       const float* __restrict__ W2, const float* __restrict__ b2) {
    if (blockIdx.x < PMAX) {
        __shared__ float eff[D];
        int p = blockIdx.x;
        int t = threadIdx.x;
        if (t < D / 2) {
            double theta = pow(10000.0, -2.0 * t / (double)D);
            double ang = (double)p * theta;
            double c = cos(ang), s = sin(ang);
            float w0 = W2[2 * t], w1 = W2[2 * t + 1];
            eff[2 * t]     = (float)(w0 * c + w1 * s);
            eff[2 * t + 1] = (float)(w1 * c - w0 * s);
        }
        __syncthreads();
        if (t < D) {
            float acc = 0.f;
#pragma unroll 8
            for (int d = 0; d < D; d++)
                acc = fmaf(W1[d * D + t], eff[d], acc);
            g_vtab[p * D + t] = acc;
            if (t == 0) {
                float cb = b2[0];
                for (int d = 0; d < D; d++) cb = fmaf(b1[d], eff[d], cb);
                g_ctab[p] = cb;
            }
        }
    } else {
        int i = (blockIdx.x - PMAX) * blockDim.x + threadIdx.x;
        if (i >= n) return;
        int b = batch[i];
        if (i == 0 || batch[i - 1] != b) {
            if (b >= 0 && b < START_SZ) g_start[b] = i;
        }
        if (i == n - 1) g_lastb = b;
    }
}

// ---------------------------------------------------------------------------
// Slow path (pos >= PMAX, never expected on this input)
// ---------------------------------------------------------------------------
__device__ float row_slow(const float4 xv, int pos,
                          const float* __restrict__ W1,
                          const float* __restrict__ b1,
                          const float* __restrict__ W2,
                          const float* __restrict__ b2, int lane) {
    float4 w2v = reinterpret_cast<const float4*>(W2)[lane];
    float eff0, eff1, eff2, eff3;
    {
        int j0 = 2 * lane;
        double th0 = pow(10000.0, -2.0 * j0 / (double)D);
        double a0 = (double)pos * th0;
        double c0 = cos(a0), s0 = sin(a0);
        eff0 = (float)(w2v.x * c0 + w2v.y * s0);
        eff1 = (float)(w2v.y * c0 - w2v.x * s0);
        int j1 = 2 * lane + 1;
        double th1 = pow(10000.0, -2.0 * j1 / (double)D);
        double a1 = (double)pos * th1;
        double c1 = cos(a1), s1 = sin(a1);
        eff2 = (float)(w2v.z * c1 + w2v.w * s1);
        eff3 = (float)(w2v.w * c1 - w2v.z * s1);
    }
    float4 acc = make_float4(0.f, 0.f, 0.f, 0.f);
    const float4* W1r = reinterpret_cast<const float4*>(W1);
    for (int src = 0; src < 32; src++) {
        float e0 = __shfl_sync(0xffffffffu, eff0, src);
        float e1 = __shfl_sync(0xffffffffu, eff1, src);
        float e2 = __shfl_sync(0xffffffffu, eff2, src);
        float e3 = __shfl_sync(0xffffffffu, eff3, src);
        float4 a = W1r[(4 * src + 0) * (D / 4) + lane];
        acc.x = fmaf(a.x, e0, acc.x); acc.y = fmaf(a.y, e0, acc.y);
        acc.z = fmaf(a.z, e0, acc.z); acc.w = fmaf(a.w, e0, acc.w);
        float4 bq = W1r[(4 * src + 1) * (D / 4) + lane];
        acc.x = fmaf(bq.x, e1, acc.x); acc.y = fmaf(bq.y, e1, acc.y);
        acc.z = fmaf(bq.z, e1, acc.z); acc.w = fmaf(bq.w, e1, acc.w);
        float4 cq = W1r[(4 * src + 2) * (D / 4) + lane];
        acc.x = fmaf(cq.x, e2, acc.x); acc.y = fmaf(cq.y, e2, acc.y);
        acc.z = fmaf(cq.z, e2, acc.z); acc.w = fmaf(cq.w, e2, acc.w);
        float4 dq = W1r[(4 * src + 3) * (D / 4) + lane];
        acc.x = fmaf(dq.x, e3, acc.x); acc.y = fmaf(dq.y, e3, acc.y);
        acc.z = fmaf(dq.z, e3, acc.z); acc.w = fmaf(dq.w, e3, acc.w);
    }
    float4 b1v = reinterpret_cast<const float4*>(b1)[lane];
    float partial = xv.x * acc.x + xv.y * acc.y + xv.z * acc.z + xv.w * acc.w
                  + b1v.x * eff0 + b1v.y * eff1 + b1v.z * eff2 + b1v.w * eff3;
#pragma unroll
    for (int o = 16; o; o >>= 1) partial += __shfl_xor_sync(0xffffffffu, partial, o);
    return partial + b2[0];
}

// 4-row chunk: xv per lane from caller; pos resolved by lanes 0..3 from b values.
__device__ __forceinline__ void chunk_compute(
    const float4 xv[4], int b_l, int i_l, int lastb, int lane,
    const int* __restrict__ batch,
    const float* __restrict__ W1, const float* __restrict__ b1,
    const float* __restrict__ W2, const float* __restrict__ b2,
    float* __restrict__ outp /* out + row0 */, int valid /* rows valid 0..4 */) {
    int pos_l = 0;
    if (lane < valid) {
        if (b_l != lastb) {
            int st;
            if (b_l >= 0 && b_l < START_SZ) st = g_start[b_l];
            else {
                int lo = 0, hi = i_l;
                while (lo < hi) { int m = (lo + hi) >> 1; if (batch[m] < b_l) lo = m + 1; else hi = m; }
                st = lo;
            }
            pos_l = i_l - st;
        }
    }
    int pos[4];
    bool any_slow = false;
    const float4* v4 = reinterpret_cast<const float4*>(g_vtab);
    float4 vv[4];
    float partial[4];
#pragma unroll
    for (int r = 0; r < 4; r++) {
        pos[r] = __shfl_sync(0xffffffffu, pos_l, r);
        int p = pos[r] < PMAX ? pos[r] : 0;
        vv[r] = v4[p * (D / 4) + lane];
        if (pos[r] >= PMAX && r < valid) any_slow = true;
    }
#pragma unroll
    for (int r = 0; r < 4; r++)
        partial[r] = xv[r].x * vv[r].x + xv[r].y * vv[r].y + xv[r].z * vv[r].z + xv[r].w * vv[r].w;
#pragma unroll
    for (int o = 16; o; o >>= 1) {
#pragma unroll
        for (int r = 0; r < 4; r++)
            partial[r] += __shfl_xor_sync(0xffffffffu, partial[r], o);
    }
    float res_l = 0.f;
#pragma unroll
    for (int r = 0; r < 4; r++) {
        float v;
        if (any_slow && pos[r] >= PMAX && r < valid)
            v = row_slow(xv[r], pos[r], W1, b1, W2, b2, lane);
        else
            v = partial[r] + g_ctab[pos[r] < PMAX ? pos[r] : 0];
        if (lane == r) res_l = v;
    }
    if (lane < valid) outp[lane] = res_l;
}

// ---------------------------------------------------------------------------
// Kernel 1: main pass — bulk-async producer + 8 consumer warps from smem
// ---------------------------------------------------------------------------
__global__ __launch_bounds__(NTHREADS)
void k_main(const float* __restrict__ x,
            const int* __restrict__ batch,
            const float* __restrict__ W1,
            const float* __restrict__ b1,
            const float* __restrict__ W2,
            const float* __restrict__ b2,
            float* __restrict__ out, int n) {
    extern __shared__ char smem[];
    const uint32_t sbase = smem_u32(smem);
    const int tid = threadIdx.x;
    const int wid = tid >> 5;
    const int lane = tid & 31;
    const int cta = blockIdx.x, C = gridDim.x;
    const int ntiles = n / TILE;
    const int lastb = __ldg(&g_lastb);

    if (tid == 0) {
#pragma unroll
        for (int s = 0; s < STAGES; s++) {
            MBAR_INIT(sbase + SM_FULL + s * 8, 1);
            MBAR_INIT(sbase + SM_EMPTY + s * 8, 8);
        }
    }
    __syncthreads();

    if (wid == 8) {
        // ---- producer (single thread) ----
        if (lane == 0) {
            int s = 0, ph = 1;
            for (int t = cta; t < ntiles; t += C) {
                MBAR_WAIT(sbase + SM_EMPTY + s * 8, ph);
                uint32_t full = sbase + SM_FULL + s * 8;
                MBAR_EXPECT_TX(full, (uint32_t)(TILE_BYTES + TILE * 4));
                BULK_G2S(sbase + SM_XBUF + s * TILE_BYTES,
                         (const void*)(x + (size_t)t * TILE * D),
                         (uint32_t)TILE_BYTES, full);
                BULK_G2S(sbase + SM_SBUF + s * TILE * 4,
                         (const void*)(batch + (size_t)t * TILE),
                         (uint32_t)(TILE * 4), full);
                if (++s == STAGES) { s = 0; ph ^= 1; }
            }
        }
    } else {
        // ---- consumers: warp wid handles rows [wid*8, wid*8+8) of each tile ----
        int s = 0, ph = 0;
        for (int t = cta; t < ntiles; t += C) {
            MBAR_WAIT(sbase + SM_FULL + s * 8, ph);
            const float4* xb = reinterpret_cast<const float4*>(smem + SM_XBUF + s * TILE_BYTES);
            const int*    sb = reinterpret_cast<const int*>(smem + SM_SBUF + s * TILE * 4);
            int base = wid * 8;
#pragma unroll
            for (int c = 0; c < 2; c++) {
                int r0 = base + c * 4;                 // row-in-tile of lane-0 row
                float4 xv[4];
#pragma unroll
                for (int r = 0; r < 4; r++)
                    xv[r] = xb[(r0 + r) * (D / 4) + lane];
                int gi = t * TILE + r0 + lane;         // global row for lane<4
                int b_l = (lane < 4) ? sb[r0 + lane] : 0;
                chunk_compute(xv, b_l, gi, lastb, lane, batch,
                              W1, b1, W2, b2, out + t * TILE + r0, 4);
            }
            if (lane == 0) MBAR_ARRIVE(sbase + SM_EMPTY + s * 8);
            if (++s == STAGES) { s = 0; ph ^= 1; }
        }
        // ---- tail rows (n % TILE), handled by one CTA via direct global loads ----
        int tail0 = ntiles * TILE;
        if (tail0 < n && cta == (ntiles % C)) {
            const float4* x4 = reinterpret_cast<const float4*>(x);
#pragma unroll 1
            for (int c = 0; c < 2; c++) {
                int r0 = tail0 + wid * 8 + c * 4;
                int valid = min(4, n - r0);
                if (valid <= 0) continue;
                float4 xv[4];
#pragma unroll
                for (int r = 0; r < 4; r++) {
                    int row = min(r0 + r, n - 1);
                    xv[r] = x4[(size_t)row * (D / 4) + lane];
                }
                int gi = min(r0 + lane, n - 1);
                int b_l = (lane < 4) ? __ldg(&batch[gi]) : 0;
                chunk_compute(xv, b_l, gi, lastb, lane, batch,
                              W1, b1, W2, b2, out + r0, valid);
            }
        }
    }
}

// ---------------------------------------------------------------------------
extern "C" void kernel_launch(void* const* d_in, const int* in_sizes, int n_in,
                              void* d_out, int out_size) {
    const float* x     = (const float*)d_in[0];
    const int*   batch = (const int*)d_in[1];   // int32 (JAX x64 disabled)
    const float* W1    = (const float*)d_in[2];
    const float* b1    = (const float*)d_in[3];
    const float* W2    = (const float*)d_in[4];
    const float* b2    = (const float*)d_in[5];
    float*       out   = (float*)d_out;
    int n = in_sizes[1];

    static bool attr_set = false;
    if (!attr_set) {
        cudaFuncSetAttribute(k_main, cudaFuncAttributeMaxDynamicSharedMemorySize, SMEM_BYTES);
        attr_set = true;
    }

    int bounds_blocks = (n + 255) / 256;
    k_prep<<<PMAX + bounds_blocks, 256>>>(batch, n, W1, b1, W2, b2);
    k_main<<<NCTA, NTHREADS, SMEM_BYTES>>>(x, batch, W1, b1, W2, b2, out, n);
}